// round 4
// baseline (speedup 1.0000x reference)
#include <cuda_runtime.h>
#include <math.h>
#include <stdint.h>

#define NTOK 1024
#define DIMV 512
#define NHEAD 8
#define DHEAD 64
#define QBV 4
#define NPAIR 32
#define NROWS 4096
#define NALL 12288
#define NSEG 32768
#define INV8 ((float)(1.0 / (8.0 + 1e-6)))

__device__ float g_XLN[(size_t)NALL * DIMV];
__device__ float g_F[(size_t)NALL * DIMV];
__device__ float g_S[(size_t)NPAIR * NTOK * NTOK];
__device__ float g_OF[(size_t)NROWS * DIMV];
__device__ float g_rncq[NSEG], g_rnsq[NSEG], g_mq[NSEG], g_aq[NSEG];
__device__ float g_rnck[NSEG], g_rnsk[NSEG], g_tk[NSEG], g_sk[NSEG];
__device__ float g_kbar[NPAIR * DHEAD], g_T[NPAIR];
__device__ float g_qg[NHEAD * DHEAD], g_kg[NHEAD * DHEAD];
__device__ float g_rpart[(size_t)NSEG * 16 * 3];       // per (row, m-block): cos,pre,margin
__device__ double g_mpart[(size_t)NPAIR * 256 * 5];    // per (pair, block): 5 moments
__device__ double g_mom[NHEAD * 9];
__device__ float g_coef[16];

// ---------------- LayerNorm of q,k,v stacked --------------------------------
__global__ void k_ln(const float* __restrict__ q, const float* __restrict__ k,
                     const float* __restrict__ v, const float* __restrict__ g,
                     const float* __restrict__ b) {
    int r = blockIdx.x;
    const float* src = (r < NROWS) ? q + (size_t)r * DIMV
                     : (r < 2 * NROWS) ? k + (size_t)(r - NROWS) * DIMV
                     : v + (size_t)(r - 2 * NROWS) * DIMV;
    int tid = threadIdx.x;  // 128
    float x[4]; float s = 0.f, s2 = 0.f;
#pragma unroll
    for (int j = 0; j < 4; j++) { x[j] = src[tid + j * 128]; s += x[j]; s2 += x[j] * x[j]; }
    __shared__ float shs[4], shs2[4];
    for (int off = 16; off >= 1; off >>= 1) {
        s += __shfl_down_sync(0xffffffffu, s, off);
        s2 += __shfl_down_sync(0xffffffffu, s2, off);
    }
    int lane = tid & 31, w = tid >> 5;
    if (lane == 0) { shs[w] = s; shs2[w] = s2; }
    __syncthreads();
    __shared__ float s_mu, s_rstd;
    if (tid == 0) {
        float S = shs[0] + shs[1] + shs[2] + shs[3];
        float S2 = shs2[0] + shs2[1] + shs2[2] + shs2[3];
        float mu = S / DIMV;
        s_mu = mu; s_rstd = rsqrtf(S2 / DIMV - mu * mu + 1e-5f);
    }
    __syncthreads();
    float mu = s_mu, rstd = s_rstd;
#pragma unroll
    for (int j = 0; j < 4; j++) {
        int c = tid + j * 128;
        g_XLN[(size_t)r * DIMV + c] = (x[j] - mu) * rstd * g[c] + b[c];
    }
}

// ---------------- generic tiled SGEMM: C = A[M,K] @ B[K,N] (+bias) ----------
__global__ void k_sgemm(const float* __restrict__ A, const float* __restrict__ B,
                        const float* __restrict__ bias, float* __restrict__ C,
                        int M, int N, int K) {
    __shared__ float As[64][17];
    __shared__ float Bs[16][64];
    int tid = threadIdx.x;
    int tx = tid & 15, ty = tid >> 4;
    int m0 = blockIdx.y * 64, n0 = blockIdx.x * 64;
    float acc[4][4] = {};
    int ar = tid >> 2, aks = (tid & 3) * 4;
    int bk = tid >> 4, bns = (tid & 15) * 4;
    for (int k0 = 0; k0 < K; k0 += 16) {
        float4 va = *(const float4*)&A[(size_t)(m0 + ar) * K + k0 + aks];
        float4 vb = *(const float4*)&B[(size_t)(k0 + bk) * N + n0 + bns];
        __syncthreads();
        As[ar][aks + 0] = va.x; As[ar][aks + 1] = va.y;
        As[ar][aks + 2] = va.z; As[ar][aks + 3] = va.w;
        *(float4*)&Bs[bk][bns] = vb;
        __syncthreads();
#pragma unroll
        for (int kk = 0; kk < 16; kk++) {
            float a0 = As[4 * ty + 0][kk], a1 = As[4 * ty + 1][kk];
            float a2 = As[4 * ty + 2][kk], a3 = As[4 * ty + 3][kk];
            float4 b4 = *(float4*)&Bs[kk][4 * tx];
            acc[0][0] += a0 * b4.x; acc[0][1] += a0 * b4.y; acc[0][2] += a0 * b4.z; acc[0][3] += a0 * b4.w;
            acc[1][0] += a1 * b4.x; acc[1][1] += a1 * b4.y; acc[1][2] += a1 * b4.z; acc[1][3] += a1 * b4.w;
            acc[2][0] += a2 * b4.x; acc[2][1] += a2 * b4.y; acc[2][2] += a2 * b4.z; acc[2][3] += a2 * b4.w;
            acc[3][0] += a3 * b4.x; acc[3][1] += a3 * b4.y; acc[3][2] += a3 * b4.z; acc[3][3] += a3 * b4.w;
        }
    }
#pragma unroll
    for (int i = 0; i < 4; i++) {
        float4 o;
        o.x = acc[i][0] + (bias ? bias[n0 + 4 * tx + 0] : 0.f);
        o.y = acc[i][1] + (bias ? bias[n0 + 4 * tx + 1] : 0.f);
        o.z = acc[i][2] + (bias ? bias[n0 + 4 * tx + 2] : 0.f);
        o.w = acc[i][3] + (bias ? bias[n0 + 4 * tx + 3] : 0.f);
        *(float4*)&C[(size_t)(m0 + 4 * ty + i) * N + n0 + 4 * tx] = o;
    }
}

// ---------------- per (row, head) stats for fq / fk -------------------------
__global__ void k_rowstats() {
    int tid = threadIdx.x;
    int w = tid >> 5, lane = tid & 31;
    int gw = blockIdx.x * 8 + w;          // 0..65535
    int tensor = gw >> 15;
    int rem = gw & 32767;
    int row = rem >> 3, h = rem & 7;
    const float* base = &g_F[(size_t)(tensor * NROWS + row) * DIMV + h * DHEAD];
    float v1 = base[lane], v2 = base[lane + 32];
    float s = v1 + v2, sq = v1 * v1 + v2 * v2;
    for (int off = 16; off >= 1; off >>= 1) {
        s += __shfl_down_sync(0xffffffffu, s, off);
        sq += __shfl_down_sync(0xffffffffu, sq, off);
    }
    if (lane == 0) {
        int sidx = h * NROWS + row;
        float nrm = sqrtf(sq);
        if (tensor == 0) {
            g_rncq[sidx] = 1.f / (nrm + 1e-8f);
            g_rnsq[sidx] = 1.f / fmaxf(nrm, 1e-6f);
            g_mq[sidx] = s * (1.f / DHEAD);
        } else {
            g_rnck[sidx] = 1.f / (nrm + 1e-8f);
            g_rnsk[sidx] = 1.f / fmaxf(nrm, 1e-6f);
            g_tk[sidx] = s;
        }
    }
}

// ---------------- kbar + T --------------------------------------------------
__global__ void k_kbar() {
    int p = blockIdx.x, h = p >> 2, qb = p & 3;
    int tid = threadIdx.x, d = tid & 63, rr = tid >> 6;
    float acc = 0.f;
    for (int m = rr; m < NTOK; m += 4)
        acc += g_F[(size_t)(NROWS + qb * NTOK + m) * DIMV + h * DHEAD + d];
    __shared__ float red[256]; __shared__ float kbv[64];
    red[tid] = acc;
    __syncthreads();
    if (rr == 0) {
        float s = red[d] + red[64 + d] + red[128 + d] + red[192 + d];
        float kb = s * (1.f / NTOK);
        g_kbar[p * DHEAD + d] = kb; kbv[d] = kb;
    }
    __syncthreads();
    if (tid == 0) {
        float t = 0.f;
        for (int i = 0; i < 64; i++) t += kbv[i];
        g_T[p] = t;
    }
}

// ---------------- a[n] = fq . kbar ; sk[m] = tk[m] - T ----------------------
__global__ void k_ask() {
    int tid = threadIdx.x, w = tid >> 5, lane = tid & 31;
    int t = blockIdx.x * 8 + w;           // 0..32767
    int p = t >> 10, n = t & 1023;
    int h = p >> 2, qb = p & 3;
    const float* fq = &g_F[(size_t)(qb * NTOK + n) * DIMV + h * DHEAD];
    const float* kb = &g_kbar[p * DHEAD];
    float s = fq[lane] * kb[lane] + fq[lane + 32] * kb[lane + 32];
    for (int off = 16; off >= 1; off >>= 1) s += __shfl_down_sync(0xffffffffu, s, off);
    if (lane == 0) { g_aq[t] = s; g_sk[t] = g_tk[t] - g_T[p]; }
}

// ---------------- qg/kg global means ---------------------------------------
__global__ void k_qgkg() {
    int h = blockIdx.x, tensor = blockIdx.y;
    int tid = threadIdx.x, d = tid & 63, rr = tid >> 6;
    float acc = 0.f;
    for (int row = rr; row < NROWS; row += 4)
        acc += g_F[(size_t)(tensor * NROWS + row) * DIMV + h * DHEAD + d];
    __shared__ float red[256];
    red[tid] = acc;
    __syncthreads();
    if (rr == 0) {
        float s = red[d] + red[64 + d] + red[128 + d] + red[192 + d];
        (tensor == 0 ? g_qg : g_kg)[h * DHEAD + d] = s * (1.f / NROWS);
    }
}

// ---------------- S = fq @ fk^T + moment partials ---------------------------
__global__ void k_sstats() {
    int p = blockIdx.z, h = p >> 2, qb = p & 3;
    int n0 = blockIdx.y * 64, m0 = blockIdx.x * 64;
    __shared__ float As[64][65];
    __shared__ float Bs[64][65];
    __shared__ float rowv[4][64];
    __shared__ float colv[3][64];
    __shared__ float wsum[8];
    int tid = threadIdx.x;
    int fqrow = qb * NTOK + n0, fkrow = NROWS + qb * NTOK + m0;
#pragma unroll
    for (int it = 0; it < 4; it++) {
        int lin = tid + it * 256;
        int r = lin >> 4, ks = (lin & 15) * 4;
        float4 va = *(const float4*)&g_F[(size_t)(fqrow + r) * DIMV + h * DHEAD + ks];
        As[r][ks + 0] = va.x; As[r][ks + 1] = va.y; As[r][ks + 2] = va.z; As[r][ks + 3] = va.w;
        float4 vb = *(const float4*)&g_F[(size_t)(fkrow + r) * DIMV + h * DHEAD + ks];
        Bs[r][ks + 0] = vb.x; Bs[r][ks + 1] = vb.y; Bs[r][ks + 2] = vb.z; Bs[r][ks + 3] = vb.w;
    }
    if (tid < 64) {
        int sr = p * NTOK + n0 + tid;
        rowv[0][tid] = g_rncq[sr]; rowv[1][tid] = g_rnsq[sr];
        rowv[2][tid] = g_aq[sr];   rowv[3][tid] = g_mq[sr];
        int sc = p * NTOK + m0 + tid;
        colv[0][tid] = g_rnck[sc]; colv[1][tid] = g_rnsk[sc]; colv[2][tid] = g_sk[sc];
    }
    __syncthreads();
    int tx = tid & 15, ty = tid >> 4;
    float acc[4][4] = {};
#pragma unroll 16
    for (int k = 0; k < 64; k++) {
        float a0 = As[4 * ty + 0][k], a1 = As[4 * ty + 1][k];
        float a2 = As[4 * ty + 2][k], a3 = As[4 * ty + 3][k];
        float b0 = Bs[4 * tx + 0][k], b1 = Bs[4 * tx + 1][k];
        float b2 = Bs[4 * tx + 2][k], b3 = Bs[4 * tx + 3][k];
        acc[0][0] += a0 * b0; acc[0][1] += a0 * b1; acc[0][2] += a0 * b2; acc[0][3] += a0 * b3;
        acc[1][0] += a1 * b0; acc[1][1] += a1 * b1; acc[1][2] += a1 * b2; acc[1][3] += a1 * b3;
        acc[2][0] += a2 * b0; acc[2][1] += a2 * b1; acc[2][2] += a2 * b2; acc[2][3] += a2 * b3;
        acc[3][0] += a3 * b0; acc[3][1] += a3 * b1; acc[3][2] += a3 * b2; acc[3][3] += a3 * b3;
    }
    float tc = 0.f, tc2 = 0.f, tp = 0.f, tp2 = 0.f, tcp = 0.f;
    float rc[4] = {}, rp[4] = {}, rm[4] = {};
    size_t sbase = ((size_t)p << 20);
#pragma unroll
    for (int i = 0; i < 4; i++) {
        int row = 4 * ty + i;
        float rq = rowv[0][row], rsq = rowv[1][row];
        float aqv = rowv[2][row], mqv = rowv[3][row];
        float4 st;
#pragma unroll
        for (int j = 0; j < 4; j++) {
            int col = 4 * tx + j;
            float sv = acc[i][j];
            float cosv = fminf(fmaxf(sv * rq * colv[0][col], -0.99f), 0.99f);
            float csim = fminf(fmaxf(sv * rsq * colv[1][col], -0.99f), 0.99f);
            float mar = fminf(fmaxf(0.01f - csim, 0.f), 10.f);
            float pre = (sv - aqv - mqv * colv[2][col]) * INV8;
            tc += cosv; tc2 += cosv * cosv;
            tp += pre;  tp2 += pre * pre; tcp += cosv * pre;
            rc[i] += cosv; rp[i] += pre; rm[i] += mar;
            (&st.x)[j] = sv;
        }
        *(float4*)&g_S[sbase + (size_t)(n0 + row) * NTOK + m0 + 4 * tx] = st;
    }
    // per-row partials (reduce over the 16 tx lanes, deterministic)
#pragma unroll
    for (int i = 0; i < 4; i++) {
        float vc = rc[i], vp = rp[i], vm = rm[i];
        for (int off = 8; off >= 1; off >>= 1) {
            vc += __shfl_xor_sync(0xffffffffu, vc, off, 16);
            vp += __shfl_xor_sync(0xffffffffu, vp, off, 16);
            vm += __shfl_xor_sync(0xffffffffu, vm, off, 16);
        }
        if (tx == 0) {
            size_t s = (size_t)(p * NTOK + n0 + 4 * ty + i) * 16 + blockIdx.x;
            g_rpart[s * 3 + 0] = vc; g_rpart[s * 3 + 1] = vp; g_rpart[s * 3 + 2] = vm;
        }
    }
    // block moment partials — indexed by PAIR p (qb must not collide!)
    float vals[5] = {tc, tc2, tp, tp2, tcp};
    int lane = tid & 31, w = tid >> 5;
    for (int v = 0; v < 5; v++) {
        float x = vals[v];
        for (int off = 16; off >= 1; off >>= 1) x += __shfl_down_sync(0xffffffffu, x, off);
        if (lane == 0) wsum[w] = x;
        __syncthreads();
        if (tid == 0) {
            float s = 0.f;
            for (int i = 0; i < 8; i++) s += wsum[i];
            g_mpart[(size_t)(p * 256 + blockIdx.y * 16 + blockIdx.x) * 5 + v] = (double)s;
        }
        __syncthreads();
    }
}

// ---------------- per-head reductions: rows + moments -----------------------
__global__ void k_rowfinish() {
    int h = blockIdx.x, tid = threadIdx.x;
    double a5 = 0, a6 = 0, a7 = 0, a8 = 0;
    for (int r = tid; r < NROWS; r += 256) {
        int s = h * NROWS + r;
        float rc = 0.f, rp = 0.f, rm = 0.f;
        for (int mb = 0; mb < 16; mb++) {
            size_t idx = ((size_t)s * 16 + mb) * 3;
            rc += g_rpart[idx]; rp += g_rpart[idx + 1]; rm += g_rpart[idx + 2];
        }
        double v = (double)rm * (1.0 / 1024.0);
        a5 += 1024.0 * v; a6 += 1024.0 * v * v;
        a7 += v * (double)rc; a8 += v * (double)rp;
    }
    __shared__ double sh[256];
    double vals[4] = {a5, a6, a7, a8};
    for (int v = 0; v < 4; v++) {
        sh[tid] = vals[v];
        __syncthreads();
        for (int s = 128; s >= 1; s >>= 1) {
            if (tid < s) sh[tid] += sh[tid + s];
            __syncthreads();
        }
        if (tid == 0) g_mom[h * 9 + 5 + v] = sh[0];
        __syncthreads();
    }
    // 5 GEMM-pass moments: 4 qb-slices x 256 blocks per head
    for (int v = 0; v < 5; v++) {
        double acc = 0.0;
        for (int qb = 0; qb < 4; qb++)
            acc += g_mpart[(size_t)((h * 4 + qb) * 256 + tid) * 5 + v];
        sh[tid] = acc;
        __syncthreads();
        for (int s = 128; s >= 1; s >>= 1) {
            if (tid < s) sh[tid] += sh[tid + s];
            __syncthreads();
        }
        if (tid == 0) g_mom[h * 9 + v] = sh[0];
        __syncthreads();
    }
}

__device__ double dev_std(double s, double s2, double N) {
    double v = (s2 - s * s / N) / (N - 1.0);
    return v > 0.0 ? sqrt(v) : 0.0;
}

// ---------------- finalize: MLP weights + global scalars --------------------
__global__ void k_finalize(const float* __restrict__ W1, const float* __restrict__ b1,
                           const float* __restrict__ lng, const float* __restrict__ lnb,
                           const float* __restrict__ W2, const float* __restrict__ b2,
                           const float* __restrict__ W3, const float* __restrict__ b3,
                           const float* __restrict__ wtp) {
    __shared__ float ws[8][3];
    int tid = threadIdx.x;
    if (tid < 8) {
        int h = tid;
        float y[64];
        for (int i = 0; i < 64; i++) {
            float a = b1[i];
            for (int j = 0; j < 64; j++) a += g_qg[h * 64 + j] * W1[j * 64 + i];
            for (int j = 0; j < 64; j++) a += g_kg[h * 64 + j] * W1[(64 + j) * 64 + i];
            y[i] = a;
        }
        float mu = 0.f;
        for (int i = 0; i < 64; i++) mu += y[i];
        mu *= (1.f / 64.f);
        float var = 0.f;
        for (int i = 0; i < 64; i++) { float d = y[i] - mu; var += d * d; }
        float rstd = rsqrtf(var * (1.f / 64.f) + 1e-5f);
        for (int i = 0; i < 64; i++)
            y[i] = fmaxf((y[i] - mu) * rstd * lng[i] + lnb[i], 0.f);
        float hh[32];
        for (int o = 0; o < 32; o++) {
            float a = b2[o];
            for (int i = 0; i < 64; i++) a += y[i] * W2[i * 32 + o];
            hh[o] = fmaxf(a, 0.f);
        }
        float l[3];
        for (int c = 0; c < 3; c++) {
            float a = b3[c];
            for (int o = 0; o < 32; o++) a += hh[o] * W3[o * 3 + c];
            l[c] = a;
        }
        float mx = fmaxf(l[0], fmaxf(l[1], l[2]));
        float e0 = expf(l[0] - mx), e1 = expf(l[1] - mx), e2 = expf(l[2] - mx);
        float sm = e0 + e1 + e2;
        l[0] = e0 / sm; l[1] = e1 / sm; l[2] = e2 / sm;
        float wt = fminf(fmaxf(wtp[0], 0.1f), 20.f);
        l[0] /= wt; l[1] /= wt; l[2] /= wt;
        mx = fmaxf(l[0], fmaxf(l[1], l[2]));
        e0 = expf(l[0] - mx); e1 = expf(l[1] - mx); e2 = expf(l[2] - mx);
        sm = e0 + e1 + e2;
        l[0] = e0 / sm; l[1] = e1 / sm; l[2] = e2 / sm;
        for (int c = 0; c < 3; c++) l[c] = fminf(fmaxf(l[c], 0.05f), 0.8f);
        sm = l[0] + l[1] + l[2];
        ws[h][0] = l[0] / sm; ws[h][1] = l[1] / sm; ws[h][2] = l[2] / sm;
    }
    __syncthreads();
    if (tid == 0) {
        const double N = 33554432.0;
        double Sc = 0, Sc2 = 0, Sp = 0, Sp2 = 0, Sv = 0, Sv2 = 0;
        for (int h = 0; h < 8; h++) {
            Sc += g_mom[h * 9 + 0]; Sc2 += g_mom[h * 9 + 1];
            Sp += g_mom[h * 9 + 2]; Sp2 += g_mom[h * 9 + 3];
            Sv += g_mom[h * 9 + 5]; Sv2 += g_mom[h * 9 + 6];
        }
        double cstd = dev_std(Sc, Sc2, N);
        double pstd = dev_std(Sp, Sp2, N);
        double vstd = dev_std(Sv, Sv2, N);
        double base = 0.001 / 1024.0;
        double reg = (pstd < 1e-6) ? base * 10.0 : base;
        double cn = cstd + 1e-6;
        double covn = reg * pstd + 1e-6;
        double vn = vstd + 1e-6;
        double cscale = (cn < 1e-4) ? 0.1 : 1.0;
        double Sd = 0, Sd2 = 0, al[8], be[8];
        for (int h = 0; h < 8; h++) {
            double a = (double)ws[h][0] * cscale / cn;
            double bb = (double)ws[h][1] * 0.5 / covn;
            double gg = (double)ws[h][2] * 0.5 / vn;
            al[h] = a; be[h] = bb;
            double m0 = g_mom[h * 9 + 0], m1 = g_mom[h * 9 + 1];
            double m2 = g_mom[h * 9 + 2], m3 = g_mom[h * 9 + 3];
            double m4 = g_mom[h * 9 + 4], m5 = g_mom[h * 9 + 5];
            double m6 = g_mom[h * 9 + 6], m7 = g_mom[h * 9 + 7];
            double m8 = g_mom[h * 9 + 8];
            Sd += a * m0 + bb * reg * m2 + gg * m5;
            Sd2 += a * a * m1 + bb * bb * reg * reg * m3 + gg * gg * m6
                 + 2.0 * a * bb * reg * m4 + 2.0 * a * gg * m7 + 2.0 * bb * gg * reg * m8;
        }
        double dvar = (Sd2 - Sd * Sd / N) / (N - 1.0);
        double dstd = dvar > 0.0 ? sqrt(dvar) : 0.0;
        double temp = (dstd < 1e-6) ? 0.1 : 0.3 + dstd;
        temp = fmin(fmax(temp, 0.1), 5.0);
        for (int h = 0; h < 8; h++) {
            g_coef[h] = (float)(al[h] / temp);
            g_coef[8 + h] = (float)(be[h] * reg / temp);
        }
    }
}

// ---------------- online softmax + AV ---------------------------------------
__global__ void k_softmaxAV() {
    int p = blockIdx.y, h = p >> 2, qb = p & 3;
    int n0 = blockIdx.x * 64;
    __shared__ float Vs[64][68];
    __shared__ float Ps[64][65];
    __shared__ float rq[64], aq_s[64], mq_s[64];
    __shared__ float rk[64], sk_s[64];
    int tid = threadIdx.x;
    int tx = tid & 15, ty = tid >> 4;
    float cA = g_coef[h], cB = g_coef[8 + h];
    if (tid < 64) {
        int s = p * NTOK + n0 + tid;
        rq[tid] = g_rncq[s]; aq_s[tid] = g_aq[s]; mq_s[tid] = g_mq[s];
    }
    float acc[4][4] = {};
    float rmax[4] = {-1e30f, -1e30f, -1e30f, -1e30f};
    float den[4] = {};
    size_t sbase = ((size_t)p << 20);
    for (int mt = 0; mt < 16; mt++) {
        int m0 = mt * 64;
        __syncthreads();
#pragma unroll
        for (int it = 0; it < 4; it++) {
            int lin = tid + it * 256;
            int r = lin >> 4, ks = (lin & 15) * 4;
            float4 v4 = *(const float4*)&g_F[(size_t)(2 * NROWS + qb * NTOK + m0 + r) * DIMV + h * DHEAD + ks];
            Vs[r][ks + 0] = v4.x; Vs[r][ks + 1] = v4.y; Vs[r][ks + 2] = v4.z; Vs[r][ks + 3] = v4.w;
        }
        if (tid < 64) {
            int s = p * NTOK + m0 + tid;
            rk[tid] = g_rnck[s]; sk_s[tid] = g_sk[s];
        }
        __syncthreads();
#pragma unroll
        for (int i = 0; i < 4; i++) {
            int row = 4 * ty + i;
            float4 s4 = *(const float4*)&g_S[sbase + (size_t)(n0 + row) * NTOK + m0 + 4 * tx];
            float rr = rq[row], av = aq_s[row], mv = mq_s[row];
            float z[4];
#pragma unroll
            for (int j = 0; j < 4; j++) {
                int col = 4 * tx + j;
                float sv = (&s4.x)[j];
                float cosv = fminf(fmaxf(sv * rr * rk[col], -0.99f), 0.99f);
                float pre = (sv - av - mv * sk_s[col]) * INV8;
                z[j] = cA * cosv + cB * pre;
            }
            float tm = fmaxf(fmaxf(z[0], z[1]), fmaxf(z[2], z[3]));
            for (int off = 8; off >= 1; off >>= 1)
                tm = fmaxf(tm, __shfl_xor_sync(0xffffffffu, tm, off, 16));
            float nm = fmaxf(rmax[i], tm);
            float corr = __expf(rmax[i] - nm);
            float ps = 0.f;
#pragma unroll
            for (int j = 0; j < 4; j++) {
                float pv = __expf(z[j] - nm);
                Ps[row][4 * tx + j] = pv;
                ps += pv;
            }
            for (int off = 8; off >= 1; off >>= 1)
                ps += __shfl_xor_sync(0xffffffffu, ps, off, 16);
            den[i] = den[i] * corr + ps;
            rmax[i] = nm;
#pragma unroll
            for (int j = 0; j < 4; j++) acc[i][j] *= corr;
        }
        __syncthreads();
#pragma unroll
        for (int i = 0; i < 4; i++) {
            int row = 4 * ty + i;
#pragma unroll 8
            for (int m = 0; m < 64; m++) {
                float pv = Ps[row][m];
                float4 v4 = *(float4*)&Vs[m][4 * tx];
                acc[i][0] += pv * v4.x; acc[i][1] += pv * v4.y;
                acc[i][2] += pv * v4.z; acc[i][3] += pv * v4.w;
            }
        }
    }
#pragma unroll
    for (int i = 0; i < 4; i++) {
        float inv = 1.f / den[i];
        int row = n0 + 4 * ty + i;
        float4 o;
        o.x = acc[i][0] * inv; o.y = acc[i][1] * inv;
        o.z = acc[i][2] * inv; o.w = acc[i][3] * inv;
        *(float4*)&g_OF[(size_t)(qb * NTOK + row) * DIMV + h * DHEAD + 4 * tx] = o;
    }
}

// ---------------- launch -----------------------------------------------------
extern "C" void kernel_launch(void* const* d_in, const int* in_sizes, int n_in,
                              void* d_out, int out_size) {
    const float* q = (const float*)d_in[0];
    const float* k = (const float*)d_in[1];
    const float* v = (const float*)d_in[2];
    const float* ln_g = (const float*)d_in[3];
    const float* ln_b = (const float*)d_in[4];
    const float* W_in = (const float*)d_in[5];
    const float* wp_W1 = (const float*)d_in[6];
    const float* wp_b1 = (const float*)d_in[7];
    const float* wp_lng = (const float*)d_in[8];
    const float* wp_lnb = (const float*)d_in[9];
    const float* wp_W2 = (const float*)d_in[10];
    const float* wp_b2 = (const float*)d_in[11];
    const float* wp_W3 = (const float*)d_in[12];
    const float* wp_b3 = (const float*)d_in[13];
    const float* wtemp = (const float*)d_in[14];
    const float* W_out = (const float*)d_in[15];
    const float* b_out = (const float*)d_in[16];
    float* out = (float*)d_out;

    float *pXLN, *pF, *pOF;
    cudaGetSymbolAddress((void**)&pXLN, g_XLN);
    cudaGetSymbolAddress((void**)&pF, g_F);
    cudaGetSymbolAddress((void**)&pOF, g_OF);

    k_ln<<<NALL, 128>>>(q, k, v, ln_g, ln_b);
    k_sgemm<<<dim3(DIMV / 64, NALL / 64), 256>>>(pXLN, W_in, nullptr, pF, NALL, DIMV, DIMV);
    k_rowstats<<<8192, 256>>>();
    k_kbar<<<NPAIR, 256>>>();
    k_ask<<<4096, 256>>>();
    k_qgkg<<<dim3(NHEAD, 2), 256>>>();
    k_sstats<<<dim3(16, 16, NPAIR), 256>>>();
    k_rowfinish<<<NHEAD, 256>>>();
    k_finalize<<<1, 32>>>(wp_W1, wp_b1, wp_lng, wp_lnb, wp_W2, wp_b2, wp_W3, wp_b3, wtemp);
    k_softmaxAV<<<dim3(16, NPAIR), 256>>>();
    k_sgemm<<<dim3(DIMV / 64, NROWS / 64), 256>>>(pOF, W_out, b_out, out, NROWS, DIMV, DIMV);
}

// round 5
// speedup vs baseline: 1.3601x; 1.3601x over previous
#include <cuda_runtime.h>
#include <math.h>
#include <stdint.h>

#define NTOK 1024
#define DIMV 512
#define NHEAD 8
#define DHEAD 64
#define QBV 4
#define NPAIR 32
#define NROWS 4096
#define NALL 12288
#define NSEG 32768
#define INV8 ((float)(1.0 / (8.0 + 1e-6)))

__device__ float g_XLN[(size_t)NALL * DIMV];
__device__ float g_F[(size_t)NALL * DIMV];
__device__ float g_S[(size_t)NPAIR * NTOK * NTOK];
__device__ float g_OF[(size_t)NROWS * DIMV];
__device__ float g_rncq[NSEG], g_rnsq[NSEG], g_mq[NSEG], g_aq[NSEG];
__device__ float g_rnck[NSEG], g_rnsk[NSEG], g_tk[NSEG], g_sk[NSEG];
__device__ float g_kbar[NPAIR * DHEAD], g_T[NPAIR];
__device__ float g_kpart[NPAIR * 8 * 64];
__device__ float g_qgpart[2 * 8 * 8 * 64];
__device__ float g_qg[NHEAD * DHEAD], g_kg[NHEAD * DHEAD];
__device__ float g_rpart[(size_t)NSEG * 8 * 3];       // per (row, m-block128): cos,pre,margin
__device__ double g_mpart[(size_t)NPAIR * 64 * 5];    // per (pair, block): 5 moments
__device__ double g_mom[NHEAD * 9];
__device__ float g_coef[16];

// ---------------- LayerNorm of q,k,v stacked --------------------------------
__global__ void k_ln(const float* __restrict__ q, const float* __restrict__ k,
                     const float* __restrict__ v, const float* __restrict__ g,
                     const float* __restrict__ b) {
    int r = blockIdx.x;
    const float* src = (r < NROWS) ? q + (size_t)r * DIMV
                     : (r < 2 * NROWS) ? k + (size_t)(r - NROWS) * DIMV
                     : v + (size_t)(r - 2 * NROWS) * DIMV;
    int tid = threadIdx.x;  // 128
    float x[4]; float s = 0.f, s2 = 0.f;
#pragma unroll
    for (int j = 0; j < 4; j++) { x[j] = src[tid + j * 128]; s += x[j]; s2 += x[j] * x[j]; }
    __shared__ float shs[4], shs2[4];
    for (int off = 16; off >= 1; off >>= 1) {
        s += __shfl_down_sync(0xffffffffu, s, off);
        s2 += __shfl_down_sync(0xffffffffu, s2, off);
    }
    int lane = tid & 31, w = tid >> 5;
    if (lane == 0) { shs[w] = s; shs2[w] = s2; }
    __syncthreads();
    __shared__ float s_mu, s_rstd;
    if (tid == 0) {
        float S = shs[0] + shs[1] + shs[2] + shs[3];
        float S2 = shs2[0] + shs2[1] + shs2[2] + shs2[3];
        float mu = S / DIMV;
        s_mu = mu; s_rstd = rsqrtf(S2 / DIMV - mu * mu + 1e-5f);
    }
    __syncthreads();
    float mu = s_mu, rstd = s_rstd;
#pragma unroll
    for (int j = 0; j < 4; j++) {
        int c = tid + j * 128;
        g_XLN[(size_t)r * DIMV + c] = (x[j] - mu) * rstd * g[c] + b[c];
    }
}

// ---------------- 128x128 tiled SGEMM: C = A[M,K] @ B[K,N] (+bias) ----------
__global__ __launch_bounds__(256) void k_sgemm(
        const float* __restrict__ A, const float* __restrict__ B,
        const float* __restrict__ bias, float* __restrict__ C,
        int M, int N, int K) {
    __shared__ float Ast[16][132];   // k-major
    __shared__ float Bs[16][132];
    int tid = threadIdx.x;
    int tx = tid & 15, ty = tid >> 4;
    int m0 = blockIdx.y * 128, n0 = blockIdx.x * 128;
    int arow = tid & 127, akg0 = tid >> 7;   // 0..1
    int bng = tid & 31, bk0 = tid >> 5;      // 0..7
    const float* Arow = A + (size_t)(m0 + arow) * K;
    float4 va[2], vb[2];
    int k0 = 0;
#pragma unroll
    for (int it = 0; it < 2; it++) {
        va[it] = *(const float4*)&Arow[k0 + (akg0 + 2 * it) * 4];
        vb[it] = *(const float4*)&B[(size_t)(k0 + bk0 + 8 * it) * N + n0 + bng * 4];
    }
    float acc[8][8] = {};
    for (int kc = 0; kc < K; kc += 16) {
        __syncthreads();
#pragma unroll
        for (int it = 0; it < 2; it++) {
            int kg = (akg0 + 2 * it) * 4;
            Ast[kg + 0][arow] = va[it].x; Ast[kg + 1][arow] = va[it].y;
            Ast[kg + 2][arow] = va[it].z; Ast[kg + 3][arow] = va[it].w;
            *(float4*)&Bs[bk0 + 8 * it][bng * 4] = vb[it];
        }
        __syncthreads();
        if (kc + 16 < K) {
            k0 = kc + 16;
#pragma unroll
            for (int it = 0; it < 2; it++) {
                va[it] = *(const float4*)&Arow[k0 + (akg0 + 2 * it) * 4];
                vb[it] = *(const float4*)&B[(size_t)(k0 + bk0 + 8 * it) * N + n0 + bng * 4];
            }
        }
#pragma unroll
        for (int kk = 0; kk < 16; kk++) {
            float4 a0 = *(float4*)&Ast[kk][8 * ty];
            float4 a1 = *(float4*)&Ast[kk][8 * ty + 4];
            float4 b0 = *(float4*)&Bs[kk][8 * tx];
            float4 b1 = *(float4*)&Bs[kk][8 * tx + 4];
            float av[8] = {a0.x, a0.y, a0.z, a0.w, a1.x, a1.y, a1.z, a1.w};
            float bv[8] = {b0.x, b0.y, b0.z, b0.w, b1.x, b1.y, b1.z, b1.w};
#pragma unroll
            for (int i = 0; i < 8; i++)
#pragma unroll
                for (int j = 0; j < 8; j++) acc[i][j] += av[i] * bv[j];
        }
    }
#pragma unroll
    for (int i = 0; i < 8; i++) {
        int row = m0 + 8 * ty + i;
#pragma unroll
        for (int jj = 0; jj < 2; jj++) {
            int col = n0 + 8 * tx + jj * 4;
            float4 o;
            o.x = acc[i][jj * 4 + 0] + (bias ? bias[col + 0] : 0.f);
            o.y = acc[i][jj * 4 + 1] + (bias ? bias[col + 1] : 0.f);
            o.z = acc[i][jj * 4 + 2] + (bias ? bias[col + 2] : 0.f);
            o.w = acc[i][jj * 4 + 3] + (bias ? bias[col + 3] : 0.f);
            *(float4*)&C[(size_t)row * N + col] = o;
        }
    }
}

// ---------------- per (row, head) stats for fq / fk -------------------------
__global__ void k_rowstats() {
    int tid = threadIdx.x;
    int w = tid >> 5, lane = tid & 31;
    int gw = blockIdx.x * 8 + w;
    int tensor = gw >> 15;
    int rem = gw & 32767;
    int row = rem >> 3, h = rem & 7;
    const float* base = &g_F[(size_t)(tensor * NROWS + row) * DIMV + h * DHEAD];
    float v1 = base[lane], v2 = base[lane + 32];
    float s = v1 + v2, sq = v1 * v1 + v2 * v2;
    for (int off = 16; off >= 1; off >>= 1) {
        s += __shfl_down_sync(0xffffffffu, s, off);
        sq += __shfl_down_sync(0xffffffffu, sq, off);
    }
    if (lane == 0) {
        int sidx = h * NROWS + row;
        float nrm = sqrtf(sq);
        if (tensor == 0) {
            g_rncq[sidx] = 1.f / (nrm + 1e-8f);
            g_rnsq[sidx] = 1.f / fmaxf(nrm, 1e-6f);
            g_mq[sidx] = s * (1.f / DHEAD);
        } else {
            g_rnck[sidx] = 1.f / (nrm + 1e-8f);
            g_rnsk[sidx] = 1.f / fmaxf(nrm, 1e-6f);
            g_tk[sidx] = s;
        }
    }
}

// ---------------- kbar two-stage --------------------------------------------
__global__ void k_kbar1() {
    int p = blockIdx.x, seg = blockIdx.y;
    int h = p >> 2, qb = p & 3;
    int tid = threadIdx.x, d = tid & 63, rr = tid >> 6;
    float acc = 0.f;
    int base = qb * NTOK + seg * 128;
    for (int m = rr; m < 128; m += 4)
        acc += g_F[(size_t)(NROWS + base + m) * DIMV + h * DHEAD + d];
    __shared__ float red[256];
    red[tid] = acc;
    __syncthreads();
    if (rr == 0) g_kpart[(p * 8 + seg) * 64 + d] = red[d] + red[64 + d] + red[128 + d] + red[192 + d];
}
__global__ void k_kbar2() {
    int p = blockIdx.x, d = threadIdx.x;   // 64 threads
    float s = 0.f;
    for (int seg = 0; seg < 8; seg++) s += g_kpart[(p * 8 + seg) * 64 + d];
    float kb = s * (1.f / NTOK);
    g_kbar[p * DHEAD + d] = kb;
    __shared__ float sh[64];
    sh[d] = kb;
    __syncthreads();
    if (d == 0) {
        float t = 0.f;
        for (int i = 0; i < 64; i++) t += sh[i];
        g_T[p] = t;
    }
}

// ---------------- a[n] = fq . kbar ; sk[m] = tk[m] - T ----------------------
__global__ void k_ask() {
    int tid = threadIdx.x, w = tid >> 5, lane = tid & 31;
    int t = blockIdx.x * 8 + w;
    int p = t >> 10, n = t & 1023;
    int h = p >> 2, qb = p & 3;
    const float* fq = &g_F[(size_t)(qb * NTOK + n) * DIMV + h * DHEAD];
    const float* kb = &g_kbar[p * DHEAD];
    float s = fq[lane] * kb[lane] + fq[lane + 32] * kb[lane + 32];
    for (int off = 16; off >= 1; off >>= 1) s += __shfl_down_sync(0xffffffffu, s, off);
    if (lane == 0) { g_aq[t] = s; g_sk[t] = g_tk[t] - g_T[p]; }
}

// ---------------- qg/kg two-stage -------------------------------------------
__global__ void k_qgkg1() {
    int h = blockIdx.x, tensor = blockIdx.y, seg = blockIdx.z;
    int tid = threadIdx.x, d = tid & 63, rr = tid >> 6;
    float acc = 0.f;
    for (int r = rr; r < 512; r += 4)
        acc += g_F[(size_t)(tensor * NROWS + seg * 512 + r) * DIMV + h * DHEAD + d];
    __shared__ float red[256];
    red[tid] = acc;
    __syncthreads();
    if (rr == 0)
        g_qgpart[((tensor * 8 + h) * 8 + seg) * 64 + d] = red[d] + red[64 + d] + red[128 + d] + red[192 + d];
}
__global__ void k_qgkg2() {
    int h = blockIdx.x, tensor = blockIdx.y, d = threadIdx.x;  // 64
    float s = 0.f;
    for (int seg = 0; seg < 8; seg++) s += g_qgpart[((tensor * 8 + h) * 8 + seg) * 64 + d];
    (tensor == 0 ? g_qg : g_kg)[h * 64 + d] = s * (1.f / NROWS);
}

// ---------------- S = fq @ fk^T (128x128 tiles) + moment partials -----------
__global__ __launch_bounds__(256) void k_sstats() {
    int p = blockIdx.z, h = p >> 2, qb = p & 3;
    int n0 = blockIdx.y * 128, m0 = blockIdx.x * 128;
    __shared__ float Aq[32][132];   // k-major
    __shared__ float Bk[32][132];
    __shared__ float rowv[4][128];
    __shared__ float colv[3][128];
    __shared__ float wsum[8];
    int tid = threadIdx.x;
    int tx = tid & 15, ty = tid >> 4;
    int lrow = tid & 127, lkg0 = tid >> 7;   // 0..1
    const float* qsrc = &g_F[(size_t)(qb * NTOK + n0 + lrow) * DIMV + h * DHEAD];
    const float* ksrc = &g_F[(size_t)(NROWS + qb * NTOK + m0 + lrow) * DIMV + h * DHEAD];
    if (tid < 128) {
        int sr = p * NTOK + n0 + tid;
        rowv[0][tid] = g_rncq[sr]; rowv[1][tid] = g_rnsq[sr];
        rowv[2][tid] = g_aq[sr];   rowv[3][tid] = g_mq[sr];
        int sc = p * NTOK + m0 + tid;
        colv[0][tid] = g_rnck[sc]; colv[1][tid] = g_rnsk[sc]; colv[2][tid] = g_sk[sc];
    }
    float4 va[4], vb[4];
    int kc = 0;
#pragma unroll
    for (int it = 0; it < 4; it++) {
        va[it] = *(const float4*)&qsrc[kc + (lkg0 + 2 * it) * 4];
        vb[it] = *(const float4*)&ksrc[kc + (lkg0 + 2 * it) * 4];
    }
    float acc[8][8] = {};
    for (int c = 0; c < 2; c++) {
        __syncthreads();
#pragma unroll
        for (int it = 0; it < 4; it++) {
            int kg = (lkg0 + 2 * it) * 4;
            Aq[kg + 0][lrow] = va[it].x; Aq[kg + 1][lrow] = va[it].y;
            Aq[kg + 2][lrow] = va[it].z; Aq[kg + 3][lrow] = va[it].w;
            Bk[kg + 0][lrow] = vb[it].x; Bk[kg + 1][lrow] = vb[it].y;
            Bk[kg + 2][lrow] = vb[it].z; Bk[kg + 3][lrow] = vb[it].w;
        }
        __syncthreads();
        if (c == 0) {
            kc = 32;
#pragma unroll
            for (int it = 0; it < 4; it++) {
                va[it] = *(const float4*)&qsrc[kc + (lkg0 + 2 * it) * 4];
                vb[it] = *(const float4*)&ksrc[kc + (lkg0 + 2 * it) * 4];
            }
        }
#pragma unroll
        for (int kk = 0; kk < 32; kk++) {
            float4 a0 = *(float4*)&Aq[kk][8 * ty];
            float4 a1 = *(float4*)&Aq[kk][8 * ty + 4];
            float4 b0 = *(float4*)&Bk[kk][8 * tx];
            float4 b1 = *(float4*)&Bk[kk][8 * tx + 4];
            float av[8] = {a0.x, a0.y, a0.z, a0.w, a1.x, a1.y, a1.z, a1.w};
            float bv[8] = {b0.x, b0.y, b0.z, b0.w, b1.x, b1.y, b1.z, b1.w};
#pragma unroll
            for (int i = 0; i < 8; i++)
#pragma unroll
                for (int j = 0; j < 8; j++) acc[i][j] += av[i] * bv[j];
        }
    }
    float tc = 0.f, tc2 = 0.f, tp = 0.f, tp2 = 0.f, tcp = 0.f;
    size_t sbase = ((size_t)p << 20);
#pragma unroll
    for (int i = 0; i < 8; i++) {
        int row = 8 * ty + i;
        float rq = rowv[0][row], rsq = rowv[1][row];
        float aqv = rowv[2][row], mqv = rowv[3][row];
        float vc = 0.f, vp = 0.f, vm = 0.f;
        float st[8];
#pragma unroll
        for (int j = 0; j < 8; j++) {
            int col = 8 * tx + j;
            float sv = acc[i][j];
            float cosv = fminf(fmaxf(sv * rq * colv[0][col], -0.99f), 0.99f);
            float csim = fminf(fmaxf(sv * rsq * colv[1][col], -0.99f), 0.99f);
            float mar = fminf(fmaxf(0.01f - csim, 0.f), 10.f);
            float pre = (sv - aqv - mqv * colv[2][col]) * INV8;
            tc += cosv; tc2 += cosv * cosv;
            tp += pre;  tp2 += pre * pre; tcp += cosv * pre;
            vc += cosv; vp += pre; vm += mar;
            st[j] = sv;
        }
        size_t so = sbase + (size_t)(n0 + row) * NTOK + m0 + 8 * tx;
        *(float4*)&g_S[so] = make_float4(st[0], st[1], st[2], st[3]);
        *(float4*)&g_S[so + 4] = make_float4(st[4], st[5], st[6], st[7]);
        for (int off = 8; off >= 1; off >>= 1) {
            vc += __shfl_xor_sync(0xffffffffu, vc, off, 16);
            vp += __shfl_xor_sync(0xffffffffu, vp, off, 16);
            vm += __shfl_xor_sync(0xffffffffu, vm, off, 16);
        }
        if (tx == 0) {
            size_t s = (size_t)(p * NTOK + n0 + row) * 8 + blockIdx.x;
            g_rpart[s * 3 + 0] = vc; g_rpart[s * 3 + 1] = vp; g_rpart[s * 3 + 2] = vm;
        }
    }
    float vals[5] = {tc, tc2, tp, tp2, tcp};
    int lane = tid & 31, w = tid >> 5;
    for (int v = 0; v < 5; v++) {
        float x = vals[v];
        for (int off = 16; off >= 1; off >>= 1) x += __shfl_down_sync(0xffffffffu, x, off);
        if (lane == 0) wsum[w] = x;
        __syncthreads();
        if (tid == 0) {
            float s = 0.f;
            for (int i = 0; i < 8; i++) s += wsum[i];
            g_mpart[(size_t)(p * 64 + blockIdx.y * 8 + blockIdx.x) * 5 + v] = (double)s;
        }
        __syncthreads();
    }
}

// ---------------- per-head reductions: rows + moments -----------------------
__global__ void k_rowfinish() {
    int h = blockIdx.x, tid = threadIdx.x;
    double a5 = 0, a6 = 0, a7 = 0, a8 = 0;
    for (int r = tid; r < NROWS; r += 256) {
        int s = h * NROWS + r;
        float rc = 0.f, rp = 0.f, rm = 0.f;
        for (int mb = 0; mb < 8; mb++) {
            size_t idx = ((size_t)s * 8 + mb) * 3;
            rc += g_rpart[idx]; rp += g_rpart[idx + 1]; rm += g_rpart[idx + 2];
        }
        double v = (double)rm * (1.0 / 1024.0);
        a5 += 1024.0 * v; a6 += 1024.0 * v * v;
        a7 += v * (double)rc; a8 += v * (double)rp;
    }
    __shared__ double sh[256];
    double vals[4] = {a5, a6, a7, a8};
    for (int v = 0; v < 4; v++) {
        sh[tid] = vals[v];
        __syncthreads();
        for (int s = 128; s >= 1; s >>= 1) {
            if (tid < s) sh[tid] += sh[tid + s];
            __syncthreads();
        }
        if (tid == 0) g_mom[h * 9 + 5 + v] = sh[0];
        __syncthreads();
    }
    // 5 GEMM-pass moments: 4 qb-slices x 64 blocks per head = 256 slots
    for (int v = 0; v < 5; v++) {
        int qb = tid >> 6, blk = tid & 63;
        sh[tid] = g_mpart[(size_t)((h * 4 + qb) * 64 + blk) * 5 + v];
        __syncthreads();
        for (int s = 128; s >= 1; s >>= 1) {
            if (tid < s) sh[tid] += sh[tid + s];
            __syncthreads();
        }
        if (tid == 0) g_mom[h * 9 + v] = sh[0];
        __syncthreads();
    }
}

__device__ double dev_std(double s, double s2, double N) {
    double v = (s2 - s * s / N) / (N - 1.0);
    return v > 0.0 ? sqrt(v) : 0.0;
}

// ---------------- finalize: MLP weights + global scalars --------------------
__global__ void k_finalize(const float* __restrict__ W1, const float* __restrict__ b1,
                           const float* __restrict__ lng, const float* __restrict__ lnb,
                           const float* __restrict__ W2, const float* __restrict__ b2,
                           const float* __restrict__ W3, const float* __restrict__ b3,
                           const float* __restrict__ wtp) {
    __shared__ float ws[8][3];
    int tid = threadIdx.x;
    if (tid < 8) {
        int h = tid;
        float y[64];
        for (int i = 0; i < 64; i++) {
            float a = b1[i];
            for (int j = 0; j < 64; j++) a += g_qg[h * 64 + j] * W1[j * 64 + i];
            for (int j = 0; j < 64; j++) a += g_kg[h * 64 + j] * W1[(64 + j) * 64 + i];
            y[i] = a;
        }
        float mu = 0.f;
        for (int i = 0; i < 64; i++) mu += y[i];
        mu *= (1.f / 64.f);
        float var = 0.f;
        for (int i = 0; i < 64; i++) { float d = y[i] - mu; var += d * d; }
        float rstd = rsqrtf(var * (1.f / 64.f) + 1e-5f);
        for (int i = 0; i < 64; i++)
            y[i] = fmaxf((y[i] - mu) * rstd * lng[i] + lnb[i], 0.f);
        float hh[32];
        for (int o = 0; o < 32; o++) {
            float a = b2[o];
            for (int i = 0; i < 64; i++) a += y[i] * W2[i * 32 + o];
            hh[o] = fmaxf(a, 0.f);
        }
        float l[3];
        for (int c = 0; c < 3; c++) {
            float a = b3[c];
            for (int o = 0; o < 32; o++) a += hh[o] * W3[o * 3 + c];
            l[c] = a;
        }
        float mx = fmaxf(l[0], fmaxf(l[1], l[2]));
        float e0 = expf(l[0] - mx), e1 = expf(l[1] - mx), e2 = expf(l[2] - mx);
        float sm = e0 + e1 + e2;
        l[0] = e0 / sm; l[1] = e1 / sm; l[2] = e2 / sm;
        float wt = fminf(fmaxf(wtp[0], 0.1f), 20.f);
        l[0] /= wt; l[1] /= wt; l[2] /= wt;
        mx = fmaxf(l[0], fmaxf(l[1], l[2]));
        e0 = expf(l[0] - mx); e1 = expf(l[1] - mx); e2 = expf(l[2] - mx);
        sm = e0 + e1 + e2;
        l[0] = e0 / sm; l[1] = e1 / sm; l[2] = e2 / sm;
        for (int c = 0; c < 3; c++) l[c] = fminf(fmaxf(l[c], 0.05f), 0.8f);
        sm = l[0] + l[1] + l[2];
        ws[h][0] = l[0] / sm; ws[h][1] = l[1] / sm; ws[h][2] = l[2] / sm;
    }
    __syncthreads();
    if (tid == 0) {
        const double N = 33554432.0;
        double Sc = 0, Sc2 = 0, Sp = 0, Sp2 = 0, Sv = 0, Sv2 = 0;
        for (int h = 0; h < 8; h++) {
            Sc += g_mom[h * 9 + 0]; Sc2 += g_mom[h * 9 + 1];
            Sp += g_mom[h * 9 + 2]; Sp2 += g_mom[h * 9 + 3];
            Sv += g_mom[h * 9 + 5]; Sv2 += g_mom[h * 9 + 6];
        }
        double cstd = dev_std(Sc, Sc2, N);
        double pstd = dev_std(Sp, Sp2, N);
        double vstd = dev_std(Sv, Sv2, N);
        double base = 0.001 / 1024.0;
        double reg = (pstd < 1e-6) ? base * 10.0 : base;
        double cn = cstd + 1e-6;
        double covn = reg * pstd + 1e-6;
        double vn = vstd + 1e-6;
        double cscale = (cn < 1e-4) ? 0.1 : 1.0;
        double Sd = 0, Sd2 = 0, al[8], be[8];
        for (int h = 0; h < 8; h++) {
            double a = (double)ws[h][0] * cscale / cn;
            double bb = (double)ws[h][1] * 0.5 / covn;
            double gg = (double)ws[h][2] * 0.5 / vn;
            al[h] = a; be[h] = bb;
            double m0 = g_mom[h * 9 + 0], m1 = g_mom[h * 9 + 1];
            double m2 = g_mom[h * 9 + 2], m3 = g_mom[h * 9 + 3];
            double m4 = g_mom[h * 9 + 4], m5 = g_mom[h * 9 + 5];
            double m6 = g_mom[h * 9 + 6], m7 = g_mom[h * 9 + 7];
            double m8 = g_mom[h * 9 + 8];
            Sd += a * m0 + bb * reg * m2 + gg * m5;
            Sd2 += a * a * m1 + bb * bb * reg * reg * m3 + gg * gg * m6
                 + 2.0 * a * bb * reg * m4 + 2.0 * a * gg * m7 + 2.0 * bb * gg * reg * m8;
        }
        double dvar = (Sd2 - Sd * Sd / N) / (N - 1.0);
        double dstd = dvar > 0.0 ? sqrt(dvar) : 0.0;
        double temp = (dstd < 1e-6) ? 0.1 : 0.3 + dstd;
        temp = fmin(fmax(temp, 0.1), 5.0);
        for (int h = 0; h < 8; h++) {
            g_coef[h] = (float)(al[h] / temp);
            g_coef[8 + h] = (float)(be[h] * reg / temp);
        }
    }
}

// ---------------- online softmax + AV ---------------------------------------
__global__ __launch_bounds__(256) void k_softmaxAV() {
    int p = blockIdx.y, h = p >> 2, qb = p & 3;
    int n0 = blockIdx.x * 64;
    __shared__ float Vs[64][68];
    __shared__ float Ps[64][65];
    __shared__ float rq[64], aq_s[64], mq_s[64];
    __shared__ float rk[64], sk_s[64];
    int tid = threadIdx.x;
    int tx = tid & 15, ty = tid >> 4;
    float cA = g_coef[h], cB = g_coef[8 + h];
    if (tid < 64) {
        int s = p * NTOK + n0 + tid;
        rq[tid] = g_rncq[s]; aq_s[tid] = g_aq[s]; mq_s[tid] = g_mq[s];
    }
    float acc[4][4] = {};
    float rmax[4] = {-1e30f, -1e30f, -1e30f, -1e30f};
    float den[4] = {};
    size_t sbase = ((size_t)p << 20);
    for (int mt = 0; mt < 16; mt++) {
        int m0 = mt * 64;
        __syncthreads();
#pragma unroll
        for (int it = 0; it < 4; it++) {
            int lin = tid + it * 256;
            int r = lin >> 4, ks = (lin & 15) * 4;
            float4 v4 = *(const float4*)&g_F[(size_t)(2 * NROWS + qb * NTOK + m0 + r) * DIMV + h * DHEAD + ks];
            Vs[r][ks + 0] = v4.x; Vs[r][ks + 1] = v4.y; Vs[r][ks + 2] = v4.z; Vs[r][ks + 3] = v4.w;
        }
        if (tid < 64) {
            int s = p * NTOK + m0 + tid;
            rk[tid] = g_rnck[s]; sk_s[tid] = g_sk[s];
        }
        __syncthreads();
#pragma unroll
        for (int i = 0; i < 4; i++) {
            int row = 4 * ty + i;
            float4 s4 = *(const float4*)&g_S[sbase + (size_t)(n0 + row) * NTOK + m0 + 4 * tx];
            float rr = rq[row], av = aq_s[row], mv = mq_s[row];
            float z[4];
#pragma unroll
            for (int j = 0; j < 4; j++) {
                int col = 4 * tx + j;
                float sv = (&s4.x)[j];
                float cosv = fminf(fmaxf(sv * rr * rk[col], -0.99f), 0.99f);
                float pre = (sv - av - mv * sk_s[col]) * INV8;
                z[j] = cA * cosv + cB * pre;
            }
            float tm = fmaxf(fmaxf(z[0], z[1]), fmaxf(z[2], z[3]));
            for (int off = 8; off >= 1; off >>= 1)
                tm = fmaxf(tm, __shfl_xor_sync(0xffffffffu, tm, off, 16));
            float nm = fmaxf(rmax[i], tm);
            float corr = __expf(rmax[i] - nm);
            float ps = 0.f;
#pragma unroll
            for (int j = 0; j < 4; j++) {
                float pv = __expf(z[j] - nm);
                Ps[row][4 * tx + j] = pv;
                ps += pv;
            }
            for (int off = 8; off >= 1; off >>= 1)
                ps += __shfl_xor_sync(0xffffffffu, ps, off, 16);
            den[i] = den[i] * corr + ps;
            rmax[i] = nm;
#pragma unroll
            for (int j = 0; j < 4; j++) acc[i][j] *= corr;
        }
        __syncthreads();
        // AV: m outer, Vs loaded once per m, Ps broadcast
#pragma unroll 4
        for (int m = 0; m < 64; m++) {
            float4 v4 = *(float4*)&Vs[m][4 * tx];
            float p0 = Ps[4 * ty + 0][m];
            float p1 = Ps[4 * ty + 1][m];
            float p2 = Ps[4 * ty + 2][m];
            float p3 = Ps[4 * ty + 3][m];
            acc[0][0] += p0 * v4.x; acc[0][1] += p0 * v4.y; acc[0][2] += p0 * v4.z; acc[0][3] += p0 * v4.w;
            acc[1][0] += p1 * v4.x; acc[1][1] += p1 * v4.y; acc[1][2] += p1 * v4.z; acc[1][3] += p1 * v4.w;
            acc[2][0] += p2 * v4.x; acc[2][1] += p2 * v4.y; acc[2][2] += p2 * v4.z; acc[2][3] += p2 * v4.w;
            acc[3][0] += p3 * v4.x; acc[3][1] += p3 * v4.y; acc[3][2] += p3 * v4.z; acc[3][3] += p3 * v4.w;
        }
    }
#pragma unroll
    for (int i = 0; i < 4; i++) {
        float inv = 1.f / den[i];
        int row = n0 + 4 * ty + i;
        float4 o;
        o.x = acc[i][0] * inv; o.y = acc[i][1] * inv;
        o.z = acc[i][2] * inv; o.w = acc[i][3] * inv;
        *(float4*)&g_OF[(size_t)(qb * NTOK + row) * DIMV + h * DHEAD + 4 * tx] = o;
    }
}

// ---------------- launch -----------------------------------------------------
extern "C" void kernel_launch(void* const* d_in, const int* in_sizes, int n_in,
                              void* d_out, int out_size) {
    const float* q = (const float*)d_in[0];
    const float* k = (const float*)d_in[1];
    const float* v = (const float*)d_in[2];
    const float* ln_g = (const float*)d_in[3];
    const float* ln_b = (const float*)d_in[4];
    const float* W_in = (const float*)d_in[5];
    const float* wp_W1 = (const float*)d_in[6];
    const float* wp_b1 = (const float*)d_in[7];
    const float* wp_lng = (const float*)d_in[8];
    const float* wp_lnb = (const float*)d_in[9];
    const float* wp_W2 = (const float*)d_in[10];
    const float* wp_b2 = (const float*)d_in[11];
    const float* wp_W3 = (const float*)d_in[12];
    const float* wp_b3 = (const float*)d_in[13];
    const float* wtemp = (const float*)d_in[14];
    const float* W_out = (const float*)d_in[15];
    const float* b_out = (const float*)d_in[16];
    float* out = (float*)d_out;

    float *pXLN, *pF, *pOF;
    cudaGetSymbolAddress((void**)&pXLN, g_XLN);
    cudaGetSymbolAddress((void**)&pF, g_F);
    cudaGetSymbolAddress((void**)&pOF, g_OF);

    k_ln<<<NALL, 128>>>(q, k, v, ln_g, ln_b);
    k_sgemm<<<dim3(DIMV / 128, NALL / 128), 256>>>(pXLN, W_in, nullptr, pF, NALL, DIMV, DIMV);
    k_rowstats<<<8192, 256>>>();
    k_kbar1<<<dim3(NPAIR, 8), 256>>>();
    k_kbar2<<<NPAIR, 64>>>();
    k_ask<<<4096, 256>>>();
    k_qgkg1<<<dim3(NHEAD, 2, 8), 256>>>();
    k_qgkg2<<<dim3(NHEAD, 2), 64>>>();
    k_sstats<<<dim3(8, 8, NPAIR), 256>>>();
    k_rowfinish<<<NHEAD, 256>>>();
    k_finalize<<<1, 32>>>(wp_W1, wp_b1, wp_lng, wp_lnb, wp_W2, wp_b2, wp_W3, wp_b3, wtemp);
    k_softmaxAV<<<dim3(16, NPAIR), 256>>>();
    k_sgemm<<<dim3(DIMV / 128, NROWS / 128), 256>>>(pOF, W_out, b_out, out, NROWS, DIMV, DIMV);
}

// round 6
// speedup vs baseline: 1.4828x; 1.0902x over previous
#include <cuda_runtime.h>
#include <math.h>
#include <stdint.h>

#define NTOK 1024
#define DIMV 512
#define NHEAD 8
#define DHEAD 64
#define QBV 4
#define NPAIR 32
#define NROWS 4096
#define NALL 12288
#define NSEG 32768
#define INV8 ((float)(1.0 / (8.0 + 1e-6)))

__device__ float g_XLN[(size_t)NALL * DIMV];
__device__ float g_F[(size_t)NALL * DIMV];
__device__ float g_S[(size_t)NPAIR * NTOK * NTOK];
__device__ float g_OF[(size_t)NROWS * DIMV];
__device__ float g_rncq[NSEG], g_rnsq[NSEG], g_mq[NSEG], g_aq[NSEG];
__device__ float g_rnck[NSEG], g_rnsk[NSEG], g_tk[NSEG], g_sk[NSEG];
__device__ float g_kbar[NPAIR * DHEAD], g_T[NPAIR];
__device__ float g_kpart[NPAIR * 8 * 64];
__device__ float g_qgpart[2 * 8 * 8 * 64];
__device__ float g_qg[NHEAD * DHEAD], g_kg[NHEAD * DHEAD];
__device__ float g_rpart[(size_t)NSEG * 8 * 3];
__device__ double g_mpart[(size_t)NPAIR * 64 * 5];
__device__ double g_mom[NHEAD * 9];
__device__ float g_coef[16];

// ---------------- helpers ---------------------------------------------------
__device__ __forceinline__ uint32_t f2tf32(float x) {
    uint32_t r;
    asm("cvt.rna.tf32.f32 %0, %1;" : "=r"(r) : "f"(x));
    return r;
}
__device__ __forceinline__ void mma_tf32(float* c, const uint32_t* a, uint32_t b0, uint32_t b1) {
    asm volatile(
        "mma.sync.aligned.m16n8k8.row.col.f32.tf32.tf32.f32 "
        "{%0,%1,%2,%3}, {%4,%5,%6,%7}, {%8,%9}, {%0,%1,%2,%3};"
        : "+f"(c[0]), "+f"(c[1]), "+f"(c[2]), "+f"(c[3])
        : "r"(a[0]), "r"(a[1]), "r"(a[2]), "r"(a[3]), "r"(b0), "r"(b1));
}

// ---------------- LayerNorm of q,k,v stacked --------------------------------
__global__ void k_ln(const float* __restrict__ q, const float* __restrict__ k,
                     const float* __restrict__ v, const float* __restrict__ g,
                     const float* __restrict__ b) {
    int r = blockIdx.x;
    const float* src = (r < NROWS) ? q + (size_t)r * DIMV
                     : (r < 2 * NROWS) ? k + (size_t)(r - NROWS) * DIMV
                     : v + (size_t)(r - 2 * NROWS) * DIMV;
    int tid = threadIdx.x;  // 128
    float x[4]; float s = 0.f, s2 = 0.f;
#pragma unroll
    for (int j = 0; j < 4; j++) { x[j] = src[tid + j * 128]; s += x[j]; s2 += x[j] * x[j]; }
    __shared__ float shs[4], shs2[4];
    for (int off = 16; off >= 1; off >>= 1) {
        s += __shfl_down_sync(0xffffffffu, s, off);
        s2 += __shfl_down_sync(0xffffffffu, s2, off);
    }
    int lane = tid & 31, w = tid >> 5;
    if (lane == 0) { shs[w] = s; shs2[w] = s2; }
    __syncthreads();
    __shared__ float s_mu, s_rstd;
    if (tid == 0) {
        float S = shs[0] + shs[1] + shs[2] + shs[3];
        float S2 = shs2[0] + shs2[1] + shs2[2] + shs2[3];
        float mu = S / DIMV;
        s_mu = mu; s_rstd = rsqrtf(S2 / DIMV - mu * mu + 1e-5f);
    }
    __syncthreads();
    float mu = s_mu, rstd = s_rstd;
#pragma unroll
    for (int j = 0; j < 4; j++) {
        int c = tid + j * 128;
        g_XLN[(size_t)r * DIMV + c] = (x[j] - mu) * rstd * g[c] + b[c];
    }
}

// ---------------- tf32x3 MMA GEMM: C = A[M,K] @ B[K,N] (+bias) --------------
// 128x128 block tile, 8 warps (4 m x 2 n), warp tile 32x64, m16n8k8 tf32.
__global__ __launch_bounds__(256) void k_mma(
        const float* __restrict__ A, const float* __restrict__ B,
        const float* __restrict__ bias, float* __restrict__ C,
        int M, int N, int K) {
    __shared__ float Ah[16][136], Al[16][136], Bh[16][136], Bl[16][136];
    int tid = threadIdx.x;
    int lane = tid & 31, wid = tid >> 5;
    int g = lane >> 2, tg = lane & 3;
    int wm = (wid & 3) * 32, wn = (wid >> 2) * 64;
    int m0 = blockIdx.y * 128, n0 = blockIdx.x * 128;
    int arow = tid & 127, akg = tid >> 7;   // 0..1
    int bng = tid & 31, bk0 = tid >> 5;     // 0..7
    const float* Arow = A + (size_t)(m0 + arow) * K;
    float4 va[2], vb[2];
#pragma unroll
    for (int it = 0; it < 2; it++) {
        va[it] = *(const float4*)&Arow[(akg + 2 * it) * 4];
        vb[it] = *(const float4*)&B[(size_t)(bk0 + 8 * it) * N + n0 + bng * 4];
    }
    float acc[2][8][4];
#pragma unroll
    for (int a = 0; a < 2; a++)
#pragma unroll
        for (int b = 0; b < 8; b++)
#pragma unroll
            for (int c = 0; c < 4; c++) acc[a][b][c] = 0.f;
    for (int kc = 0; kc < K; kc += 16) {
        __syncthreads();
#pragma unroll
        for (int it = 0; it < 2; it++) {
            int kka = (akg + 2 * it) * 4;
            float xs[4] = {va[it].x, va[it].y, va[it].z, va[it].w};
#pragma unroll
            for (int c = 0; c < 4; c++) {
                float hf = __uint_as_float(f2tf32(xs[c]));
                Ah[kka + c][arow] = hf;
                Al[kka + c][arow] = __uint_as_float(f2tf32(xs[c] - hf));
            }
            int kkb = bk0 + 8 * it;
            float ys[4] = {vb[it].x, vb[it].y, vb[it].z, vb[it].w};
            float hb[4], lb[4];
#pragma unroll
            for (int c = 0; c < 4; c++) {
                hb[c] = __uint_as_float(f2tf32(ys[c]));
                lb[c] = __uint_as_float(f2tf32(ys[c] - hb[c]));
            }
            *(float4*)&Bh[kkb][bng * 4] = make_float4(hb[0], hb[1], hb[2], hb[3]);
            *(float4*)&Bl[kkb][bng * 4] = make_float4(lb[0], lb[1], lb[2], lb[3]);
        }
        __syncthreads();
        if (kc + 16 < K) {
            int k0 = kc + 16;
#pragma unroll
            for (int it = 0; it < 2; it++) {
                va[it] = *(const float4*)&Arow[k0 + (akg + 2 * it) * 4];
                vb[it] = *(const float4*)&B[(size_t)(k0 + bk0 + 8 * it) * N + n0 + bng * 4];
            }
        }
#pragma unroll
        for (int ks = 0; ks < 16; ks += 8) {
            uint32_t ah[2][4], al_[2][4];
#pragma unroll
            for (int mt = 0; mt < 2; mt++) {
                int mb = wm + mt * 16 + g;
                ah[mt][0] = __float_as_uint(Ah[ks + tg][mb]);
                ah[mt][1] = __float_as_uint(Ah[ks + tg][mb + 8]);
                ah[mt][2] = __float_as_uint(Ah[ks + tg + 4][mb]);
                ah[mt][3] = __float_as_uint(Ah[ks + tg + 4][mb + 8]);
                al_[mt][0] = __float_as_uint(Al[ks + tg][mb]);
                al_[mt][1] = __float_as_uint(Al[ks + tg][mb + 8]);
                al_[mt][2] = __float_as_uint(Al[ks + tg + 4][mb]);
                al_[mt][3] = __float_as_uint(Al[ks + tg + 4][mb + 8]);
            }
#pragma unroll
            for (int nt = 0; nt < 8; nt++) {
                int nb = wn + nt * 8 + g;
                uint32_t bh0 = __float_as_uint(Bh[ks + tg][nb]);
                uint32_t bh1 = __float_as_uint(Bh[ks + tg + 4][nb]);
                uint32_t bl0 = __float_as_uint(Bl[ks + tg][nb]);
                uint32_t bl1 = __float_as_uint(Bl[ks + tg + 4][nb]);
#pragma unroll
                for (int mt = 0; mt < 2; mt++) {
                    mma_tf32(acc[mt][nt], ah[mt], bh0, bh1);
                    mma_tf32(acc[mt][nt], ah[mt], bl0, bl1);
                    mma_tf32(acc[mt][nt], al_[mt], bh0, bh1);
                }
            }
        }
    }
#pragma unroll
    for (int mt = 0; mt < 2; mt++) {
        int row0 = m0 + wm + mt * 16 + g;
#pragma unroll
        for (int nt = 0; nt < 8; nt++) {
            int col = n0 + wn + nt * 8 + 2 * tg;
            float bx = bias ? bias[col] : 0.f;
            float by = bias ? bias[col + 1] : 0.f;
            *(float2*)&C[(size_t)row0 * N + col] =
                make_float2(acc[mt][nt][0] + bx, acc[mt][nt][1] + by);
            *(float2*)&C[(size_t)(row0 + 8) * N + col] =
                make_float2(acc[mt][nt][2] + bx, acc[mt][nt][3] + by);
        }
    }
}

// ---------------- per (row, head) stats for fq / fk -------------------------
__global__ void k_rowstats() {
    int tid = threadIdx.x;
    int w = tid >> 5, lane = tid & 31;
    int gw = blockIdx.x * 8 + w;
    int tensor = gw >> 15;
    int rem = gw & 32767;
    int row = rem >> 3, h = rem & 7;
    const float* base = &g_F[(size_t)(tensor * NROWS + row) * DIMV + h * DHEAD];
    float v1 = base[lane], v2 = base[lane + 32];
    float s = v1 + v2, sq = v1 * v1 + v2 * v2;
    for (int off = 16; off >= 1; off >>= 1) {
        s += __shfl_down_sync(0xffffffffu, s, off);
        sq += __shfl_down_sync(0xffffffffu, sq, off);
    }
    if (lane == 0) {
        int sidx = h * NROWS + row;
        float nrm = sqrtf(sq);
        if (tensor == 0) {
            g_rncq[sidx] = 1.f / (nrm + 1e-8f);
            g_rnsq[sidx] = 1.f / fmaxf(nrm, 1e-6f);
            g_mq[sidx] = s * (1.f / DHEAD);
        } else {
            g_rnck[sidx] = 1.f / (nrm + 1e-8f);
            g_rnsk[sidx] = 1.f / fmaxf(nrm, 1e-6f);
            g_tk[sidx] = s;
        }
    }
}

// ---------------- kbar two-stage --------------------------------------------
__global__ void k_kbar1() {
    int p = blockIdx.x, seg = blockIdx.y;
    int h = p >> 2, qb = p & 3;
    int tid = threadIdx.x, d = tid & 63, rr = tid >> 6;
    float acc = 0.f;
    int base = qb * NTOK + seg * 128;
    for (int m = rr; m < 128; m += 4)
        acc += g_F[(size_t)(NROWS + base + m) * DIMV + h * DHEAD + d];
    __shared__ float red[256];
    red[tid] = acc;
    __syncthreads();
    if (rr == 0) g_kpart[(p * 8 + seg) * 64 + d] = red[d] + red[64 + d] + red[128 + d] + red[192 + d];
}
__global__ void k_kbar2() {
    int p = blockIdx.x, d = threadIdx.x;
    float s = 0.f;
    for (int seg = 0; seg < 8; seg++) s += g_kpart[(p * 8 + seg) * 64 + d];
    float kb = s * (1.f / NTOK);
    g_kbar[p * DHEAD + d] = kb;
    __shared__ float sh[64];
    sh[d] = kb;
    __syncthreads();
    if (d == 0) {
        float t = 0.f;
        for (int i = 0; i < 64; i++) t += sh[i];
        g_T[p] = t;
    }
}

// ---------------- a[n] = fq . kbar ; sk[m] = tk[m] - T ----------------------
__global__ void k_ask() {
    int tid = threadIdx.x, w = tid >> 5, lane = tid & 31;
    int t = blockIdx.x * 8 + w;
    int p = t >> 10, n = t & 1023;
    int h = p >> 2, qb = p & 3;
    const float* fq = &g_F[(size_t)(qb * NTOK + n) * DIMV + h * DHEAD];
    const float* kb = &g_kbar[p * DHEAD];
    float s = fq[lane] * kb[lane] + fq[lane + 32] * kb[lane + 32];
    for (int off = 16; off >= 1; off >>= 1) s += __shfl_down_sync(0xffffffffu, s, off);
    if (lane == 0) { g_aq[t] = s; g_sk[t] = g_tk[t] - g_T[p]; }
}

// ---------------- qg/kg two-stage -------------------------------------------
__global__ void k_qgkg1() {
    int h = blockIdx.x, tensor = blockIdx.y, seg = blockIdx.z;
    int tid = threadIdx.x, d = tid & 63, rr = tid >> 6;
    float acc = 0.f;
    for (int r = rr; r < 512; r += 4)
        acc += g_F[(size_t)(tensor * NROWS + seg * 512 + r) * DIMV + h * DHEAD + d];
    __shared__ float red[256];
    red[tid] = acc;
    __syncthreads();
    if (rr == 0)
        g_qgpart[((tensor * 8 + h) * 8 + seg) * 64 + d] = red[d] + red[64 + d] + red[128 + d] + red[192 + d];
}
__global__ void k_qgkg2() {
    int h = blockIdx.x, tensor = blockIdx.y, d = threadIdx.x;
    float s = 0.f;
    for (int seg = 0; seg < 8; seg++) s += g_qgpart[((tensor * 8 + h) * 8 + seg) * 64 + d];
    (tensor == 0 ? g_qg : g_kg)[h * 64 + d] = s * (1.f / NROWS);
}

// ---------------- S = fq @ fk^T (128x128 tiles) + moment partials -----------
__global__ __launch_bounds__(256) void k_sstats() {
    int p = blockIdx.z, h = p >> 2, qb = p & 3;
    int n0 = blockIdx.y * 128, m0 = blockIdx.x * 128;
    __shared__ float Aq[32][132];
    __shared__ float Bk[32][132];
    __shared__ float rowv[4][128];
    __shared__ float colv[3][128];
    __shared__ float wsum[8];
    int tid = threadIdx.x;
    int tx = tid & 15, ty = tid >> 4;
    int lrow = tid & 127, lkg0 = tid >> 7;
    const float* qsrc = &g_F[(size_t)(qb * NTOK + n0 + lrow) * DIMV + h * DHEAD];
    const float* ksrc = &g_F[(size_t)(NROWS + qb * NTOK + m0 + lrow) * DIMV + h * DHEAD];
    if (tid < 128) {
        int sr = p * NTOK + n0 + tid;
        rowv[0][tid] = g_rncq[sr]; rowv[1][tid] = g_rnsq[sr];
        rowv[2][tid] = g_aq[sr];   rowv[3][tid] = g_mq[sr];
        int sc = p * NTOK + m0 + tid;
        colv[0][tid] = g_rnck[sc]; colv[1][tid] = g_rnsk[sc]; colv[2][tid] = g_sk[sc];
    }
    float4 va[4], vb[4];
    int kc = 0;
#pragma unroll
    for (int it = 0; it < 4; it++) {
        va[it] = *(const float4*)&qsrc[kc + (lkg0 + 2 * it) * 4];
        vb[it] = *(const float4*)&ksrc[kc + (lkg0 + 2 * it) * 4];
    }
    float acc[8][8] = {};
    for (int c = 0; c < 2; c++) {
        __syncthreads();
#pragma unroll
        for (int it = 0; it < 4; it++) {
            int kg = (lkg0 + 2 * it) * 4;
            Aq[kg + 0][lrow] = va[it].x; Aq[kg + 1][lrow] = va[it].y;
            Aq[kg + 2][lrow] = va[it].z; Aq[kg + 3][lrow] = va[it].w;
            Bk[kg + 0][lrow] = vb[it].x; Bk[kg + 1][lrow] = vb[it].y;
            Bk[kg + 2][lrow] = vb[it].z; Bk[kg + 3][lrow] = vb[it].w;
        }
        __syncthreads();
        if (c == 0) {
            kc = 32;
#pragma unroll
            for (int it = 0; it < 4; it++) {
                va[it] = *(const float4*)&qsrc[kc + (lkg0 + 2 * it) * 4];
                vb[it] = *(const float4*)&ksrc[kc + (lkg0 + 2 * it) * 4];
            }
        }
#pragma unroll
        for (int kk = 0; kk < 32; kk++) {
            float4 a0 = *(float4*)&Aq[kk][8 * ty];
            float4 a1 = *(float4*)&Aq[kk][8 * ty + 4];
            float4 b0 = *(float4*)&Bk[kk][8 * tx];
            float4 b1 = *(float4*)&Bk[kk][8 * tx + 4];
            float av[8] = {a0.x, a0.y, a0.z, a0.w, a1.x, a1.y, a1.z, a1.w};
            float bv[8] = {b0.x, b0.y, b0.z, b0.w, b1.x, b1.y, b1.z, b1.w};
#pragma unroll
            for (int i = 0; i < 8; i++)
#pragma unroll
                for (int j = 0; j < 8; j++) acc[i][j] += av[i] * bv[j];
        }
    }
    float tc = 0.f, tc2 = 0.f, tp = 0.f, tp2 = 0.f, tcp = 0.f;
    size_t sbase = ((size_t)p << 20);
#pragma unroll
    for (int i = 0; i < 8; i++) {
        int row = 8 * ty + i;
        float rq = rowv[0][row], rsq = rowv[1][row];
        float aqv = rowv[2][row], mqv = rowv[3][row];
        float vc = 0.f, vp = 0.f, vm = 0.f;
        float st[8];
#pragma unroll
        for (int j = 0; j < 8; j++) {
            int col = 8 * tx + j;
            float sv = acc[i][j];
            float cosv = fminf(fmaxf(sv * rq * colv[0][col], -0.99f), 0.99f);
            float csim = fminf(fmaxf(sv * rsq * colv[1][col], -0.99f), 0.99f);
            float mar = fminf(fmaxf(0.01f - csim, 0.f), 10.f);
            float pre = (sv - aqv - mqv * colv[2][col]) * INV8;
            tc += cosv; tc2 += cosv * cosv;
            tp += pre;  tp2 += pre * pre; tcp += cosv * pre;
            vc += cosv; vp += pre; vm += mar;
            st[j] = sv;
        }
        size_t so = sbase + (size_t)(n0 + row) * NTOK + m0 + 8 * tx;
        *(float4*)&g_S[so] = make_float4(st[0], st[1], st[2], st[3]);
        *(float4*)&g_S[so + 4] = make_float4(st[4], st[5], st[6], st[7]);
        for (int off = 8; off >= 1; off >>= 1) {
            vc += __shfl_xor_sync(0xffffffffu, vc, off, 16);
            vp += __shfl_xor_sync(0xffffffffu, vp, off, 16);
            vm += __shfl_xor_sync(0xffffffffu, vm, off, 16);
        }
        if (tx == 0) {
            size_t s = (size_t)(p * NTOK + n0 + row) * 8 + blockIdx.x;
            g_rpart[s * 3 + 0] = vc; g_rpart[s * 3 + 1] = vp; g_rpart[s * 3 + 2] = vm;
        }
    }
    float vals[5] = {tc, tc2, tp, tp2, tcp};
    int lane = tid & 31, w = tid >> 5;
    for (int v = 0; v < 5; v++) {
        float x = vals[v];
        for (int off = 16; off >= 1; off >>= 1) x += __shfl_down_sync(0xffffffffu, x, off);
        if (lane == 0) wsum[w] = x;
        __syncthreads();
        if (tid == 0) {
            float s = 0.f;
            for (int i = 0; i < 8; i++) s += wsum[i];
            g_mpart[(size_t)(p * 64 + blockIdx.y * 8 + blockIdx.x) * 5 + v] = (double)s;
        }
        __syncthreads();
    }
}

// ---------------- per-head reductions: rows + moments -----------------------
__global__ void k_rowfinish() {
    int h = blockIdx.x, tid = threadIdx.x;
    double a5 = 0, a6 = 0, a7 = 0, a8 = 0;
    for (int r = tid; r < NROWS; r += 256) {
        int s = h * NROWS + r;
        float rc = 0.f, rp = 0.f, rm = 0.f;
        for (int mb = 0; mb < 8; mb++) {
            size_t idx = ((size_t)s * 8 + mb) * 3;
            rc += g_rpart[idx]; rp += g_rpart[idx + 1]; rm += g_rpart[idx + 2];
        }
        double v = (double)rm * (1.0 / 1024.0);
        a5 += 1024.0 * v; a6 += 1024.0 * v * v;
        a7 += v * (double)rc; a8 += v * (double)rp;
    }
    __shared__ double sh[256];
    double vals[4] = {a5, a6, a7, a8};
    for (int v = 0; v < 4; v++) {
        sh[tid] = vals[v];
        __syncthreads();
        for (int s = 128; s >= 1; s >>= 1) {
            if (tid < s) sh[tid] += sh[tid + s];
            __syncthreads();
        }
        if (tid == 0) g_mom[h * 9 + 5 + v] = sh[0];
        __syncthreads();
    }
    for (int v = 0; v < 5; v++) {
        int qb = tid >> 6, blk = tid & 63;
        sh[tid] = g_mpart[(size_t)((h * 4 + qb) * 64 + blk) * 5 + v];
        __syncthreads();
        for (int s = 128; s >= 1; s >>= 1) {
            if (tid < s) sh[tid] += sh[tid + s];
            __syncthreads();
        }
        if (tid == 0) g_mom[h * 9 + v] = sh[0];
        __syncthreads();
    }
}

__device__ double dev_std(double s, double s2, double N) {
    double v = (s2 - s * s / N) / (N - 1.0);
    return v > 0.0 ? sqrt(v) : 0.0;
}

// ---------------- finalize: MLP weights + global scalars --------------------
__global__ void k_finalize(const float* __restrict__ W1, const float* __restrict__ b1,
                           const float* __restrict__ lng, const float* __restrict__ lnb,
                           const float* __restrict__ W2, const float* __restrict__ b2,
                           const float* __restrict__ W3, const float* __restrict__ b3,
                           const float* __restrict__ wtp) {
    __shared__ float ws[8][3];
    int tid = threadIdx.x;
    if (tid < 8) {
        int h = tid;
        float y[64];
        for (int i = 0; i < 64; i++) {
            float a = b1[i];
            for (int j = 0; j < 64; j++) a += g_qg[h * 64 + j] * W1[j * 64 + i];
            for (int j = 0; j < 64; j++) a += g_kg[h * 64 + j] * W1[(64 + j) * 64 + i];
            y[i] = a;
        }
        float mu = 0.f;
        for (int i = 0; i < 64; i++) mu += y[i];
        mu *= (1.f / 64.f);
        float var = 0.f;
        for (int i = 0; i < 64; i++) { float d = y[i] - mu; var += d * d; }
        float rstd = rsqrtf(var * (1.f / 64.f) + 1e-5f);
        for (int i = 0; i < 64; i++)
            y[i] = fmaxf((y[i] - mu) * rstd * lng[i] + lnb[i], 0.f);
        float hh[32];
        for (int o = 0; o < 32; o++) {
            float a = b2[o];
            for (int i = 0; i < 64; i++) a += y[i] * W2[i * 32 + o];
            hh[o] = fmaxf(a, 0.f);
        }
        float l[3];
        for (int c = 0; c < 3; c++) {
            float a = b3[c];
            for (int o = 0; o < 32; o++) a += hh[o] * W3[o * 3 + c];
            l[c] = a;
        }
        float mx = fmaxf(l[0], fmaxf(l[1], l[2]));
        float e0 = expf(l[0] - mx), e1 = expf(l[1] - mx), e2 = expf(l[2] - mx);
        float sm = e0 + e1 + e2;
        l[0] = e0 / sm; l[1] = e1 / sm; l[2] = e2 / sm;
        float wt = fminf(fmaxf(wtp[0], 0.1f), 20.f);
        l[0] /= wt; l[1] /= wt; l[2] /= wt;
        mx = fmaxf(l[0], fmaxf(l[1], l[2]));
        e0 = expf(l[0] - mx); e1 = expf(l[1] - mx); e2 = expf(l[2] - mx);
        sm = e0 + e1 + e2;
        l[0] = e0 / sm; l[1] = e1 / sm; l[2] = e2 / sm;
        for (int c = 0; c < 3; c++) l[c] = fminf(fmaxf(l[c], 0.05f), 0.8f);
        sm = l[0] + l[1] + l[2];
        ws[h][0] = l[0] / sm; ws[h][1] = l[1] / sm; ws[h][2] = l[2] / sm;
    }
    __syncthreads();
    if (tid == 0) {
        const double N = 33554432.0;
        double Sc = 0, Sc2 = 0, Sp = 0, Sp2 = 0, Sv = 0, Sv2 = 0;
        for (int h = 0; h < 8; h++) {
            Sc += g_mom[h * 9 + 0]; Sc2 += g_mom[h * 9 + 1];
            Sp += g_mom[h * 9 + 2]; Sp2 += g_mom[h * 9 + 3];
            Sv += g_mom[h * 9 + 5]; Sv2 += g_mom[h * 9 + 6];
        }
        double cstd = dev_std(Sc, Sc2, N);
        double pstd = dev_std(Sp, Sp2, N);
        double vstd = dev_std(Sv, Sv2, N);
        double base = 0.001 / 1024.0;
        double reg = (pstd < 1e-6) ? base * 10.0 : base;
        double cn = cstd + 1e-6;
        double covn = reg * pstd + 1e-6;
        double vn = vstd + 1e-6;
        double cscale = (cn < 1e-4) ? 0.1 : 1.0;
        double Sd = 0, Sd2 = 0, al[8], be[8];
        for (int h = 0; h < 8; h++) {
            double a = (double)ws[h][0] * cscale / cn;
            double bb = (double)ws[h][1] * 0.5 / covn;
            double gg = (double)ws[h][2] * 0.5 / vn;
            al[h] = a; be[h] = bb;
            double m0 = g_mom[h * 9 + 0], m1 = g_mom[h * 9 + 1];
            double m2 = g_mom[h * 9 + 2], m3 = g_mom[h * 9 + 3];
            double m4 = g_mom[h * 9 + 4], m5 = g_mom[h * 9 + 5];
            double m6 = g_mom[h * 9 + 6], m7 = g_mom[h * 9 + 7];
            double m8 = g_mom[h * 9 + 8];
            Sd += a * m0 + bb * reg * m2 + gg * m5;
            Sd2 += a * a * m1 + bb * bb * reg * reg * m3 + gg * gg * m6
                 + 2.0 * a * bb * reg * m4 + 2.0 * a * gg * m7 + 2.0 * bb * gg * reg * m8;
        }
        double dvar = (Sd2 - Sd * Sd / N) / (N - 1.0);
        double dstd = dvar > 0.0 ? sqrt(dvar) : 0.0;
        double temp = (dstd < 1e-6) ? 0.1 : 0.3 + dstd;
        temp = fmin(fmax(temp, 0.1), 5.0);
        for (int h = 0; h < 8; h++) {
            g_coef[h] = (float)(al[h] / temp);
            g_coef[8 + h] = (float)(be[h] * reg / temp);
        }
    }
}

// ---------------- online softmax + AV (128-row blocks, dyn smem) ------------
#define VS_PITCH 68
#define PS_PITCH 69
#define SMAV_FLOATS (64 * VS_PITCH + 128 * PS_PITCH + 128 * 3 + 64 * 2)
__global__ __launch_bounds__(256) void k_softmaxAV() {
    extern __shared__ float smp[];
    float (*Vs)[VS_PITCH] = (float(*)[VS_PITCH])smp;
    float (*Ps)[PS_PITCH] = (float(*)[PS_PITCH])(smp + 64 * VS_PITCH);
    float* rq = smp + 64 * VS_PITCH + 128 * PS_PITCH;
    float* aqv = rq + 128;
    float* mqv = aqv + 128;
    float* rk = mqv + 128;
    float* skv = rk + 64;
    int p = blockIdx.y, h = p >> 2, qb = p & 3;
    int n0 = blockIdx.x * 128;
    int tid = threadIdx.x;
    int tx = tid & 15, ty = tid >> 4;
    float cA = g_coef[h], cB = g_coef[8 + h];
    if (tid < 128) {
        int s = p * NTOK + n0 + tid;
        rq[tid] = g_rncq[s]; aqv[tid] = g_aq[s]; mqv[tid] = g_mq[s];
    }
    float acc[8][4] = {};
    float rmax[8], den[8] = {};
#pragma unroll
    for (int i = 0; i < 8; i++) rmax[i] = -1e30f;
    size_t sbase = ((size_t)p << 20);
    for (int mt = 0; mt < 16; mt++) {
        int m0 = mt * 64;
        __syncthreads();
#pragma unroll
        for (int it = 0; it < 4; it++) {
            int lin = tid + it * 256;
            int r = lin >> 4, ks = (lin & 15) * 4;
            float4 v4 = *(const float4*)&g_F[(size_t)(2 * NROWS + qb * NTOK + m0 + r) * DIMV + h * DHEAD + ks];
            Vs[r][ks + 0] = v4.x; Vs[r][ks + 1] = v4.y; Vs[r][ks + 2] = v4.z; Vs[r][ks + 3] = v4.w;
        }
        if (tid < 64) {
            int s = p * NTOK + m0 + tid;
            rk[tid] = g_rnck[s]; skv[tid] = g_sk[s];
        }
        __syncthreads();
        // phase 1: z, online softmax, write P (rows 8*ty+i, cols 4*tx+j)
#pragma unroll
        for (int i = 0; i < 8; i++) {
            int row = 8 * ty + i;
            float4 s4 = *(const float4*)&g_S[sbase + (size_t)(n0 + row) * NTOK + m0 + 4 * tx];
            float rr = rq[row], av = aqv[row], mv = mqv[row];
            float z[4];
#pragma unroll
            for (int j = 0; j < 4; j++) {
                int col = 4 * tx + j;
                float sv = (&s4.x)[j];
                float cosv = fminf(fmaxf(sv * rr * rk[col], -0.99f), 0.99f);
                float pre = (sv - av - mv * skv[col]) * INV8;
                z[j] = cA * cosv + cB * pre;
            }
            float tm = fmaxf(fmaxf(z[0], z[1]), fmaxf(z[2], z[3]));
            for (int off = 8; off >= 1; off >>= 1)
                tm = fmaxf(tm, __shfl_xor_sync(0xffffffffu, tm, off, 16));
            float nm = fmaxf(rmax[i], tm);
            float corr = __expf(rmax[i] - nm);
            float ps = 0.f;
#pragma unroll
            for (int j = 0; j < 4; j++) {
                float pv = __expf(z[j] - nm);
                Ps[row][4 * tx + j] = pv;
                ps += pv;
            }
            for (int off = 8; off >= 1; off >>= 1)
                ps += __shfl_xor_sync(0xffffffffu, ps, off, 16);
            den[i] = den[i] * corr + ps;
            rmax[i] = nm;
#pragma unroll
            for (int j = 0; j < 4; j++) acc[i][j] *= corr;
        }
        __syncthreads();
        // phase 2: AV — rows 8*ty+i, d-cols 4*tx+j
#pragma unroll 4
        for (int m = 0; m < 64; m++) {
            float4 v4 = *(float4*)&Vs[m][4 * tx];
#pragma unroll
            for (int i = 0; i < 8; i++) {
                float pv = Ps[8 * ty + i][m];
                acc[i][0] += pv * v4.x; acc[i][1] += pv * v4.y;
                acc[i][2] += pv * v4.z; acc[i][3] += pv * v4.w;
            }
        }
    }
#pragma unroll
    for (int i = 0; i < 8; i++) {
        float inv = 1.f / den[i];
        int row = n0 + 8 * ty + i;
        float4 o;
        o.x = acc[i][0] * inv; o.y = acc[i][1] * inv;
        o.z = acc[i][2] * inv; o.w = acc[i][3] * inv;
        *(float4*)&g_OF[(size_t)(qb * NTOK + row) * DIMV + h * DHEAD + 4 * tx] = o;
    }
}

// ---------------- launch -----------------------------------------------------
extern "C" void kernel_launch(void* const* d_in, const int* in_sizes, int n_in,
                              void* d_out, int out_size) {
    const float* q = (const float*)d_in[0];
    const float* k = (const float*)d_in[1];
    const float* v = (const float*)d_in[2];
    const float* ln_g = (const float*)d_in[3];
    const float* ln_b = (const float*)d_in[4];
    const float* W_in = (const float*)d_in[5];
    const float* wp_W1 = (const float*)d_in[6];
    const float* wp_b1 = (const float*)d_in[7];
    const float* wp_lng = (const float*)d_in[8];
    const float* wp_lnb = (const float*)d_in[9];
    const float* wp_W2 = (const float*)d_in[10];
    const float* wp_b2 = (const float*)d_in[11];
    const float* wp_W3 = (const float*)d_in[12];
    const float* wp_b3 = (const float*)d_in[13];
    const float* wtemp = (const float*)d_in[14];
    const float* W_out = (const float*)d_in[15];
    const float* b_out = (const float*)d_in[16];
    float* out = (float*)d_out;

    float *pXLN, *pF, *pOF;
    cudaGetSymbolAddress((void**)&pXLN, g_XLN);
    cudaGetSymbolAddress((void**)&pF, g_F);
    cudaGetSymbolAddress((void**)&pOF, g_OF);

    cudaFuncSetAttribute(k_softmaxAV, cudaFuncAttributeMaxDynamicSharedMemorySize,
                         SMAV_FLOATS * sizeof(float));

    k_ln<<<NALL, 128>>>(q, k, v, ln_g, ln_b);
    k_mma<<<dim3(DIMV / 128, NALL / 128), 256>>>(pXLN, W_in, nullptr, pF, NALL, DIMV, DIMV);
    k_rowstats<<<8192, 256>>>();
    k_kbar1<<<dim3(NPAIR, 8), 256>>>();
    k_kbar2<<<NPAIR, 64>>>();
    k_ask<<<4096, 256>>>();
    k_qgkg1<<<dim3(NHEAD, 2, 8), 256>>>();
    k_qgkg2<<<dim3(NHEAD, 2), 64>>>();
    k_sstats<<<dim3(8, 8, NPAIR), 256>>>();
    k_rowfinish<<<NHEAD, 256>>>();
    k_finalize<<<1, 32>>>(wp_W1, wp_b1, wp_lng, wp_lnb, wp_W2, wp_b2, wp_W3, wp_b3, wtemp);
    k_softmaxAV<<<dim3(8, NPAIR), 256, SMAV_FLOATS * sizeof(float)>>>();
    k_mma<<<dim3(DIMV / 128, NROWS / 128), 256>>>(pOF, W_out, b_out, out, NROWS, DIMV, DIMV);
}